// round 5
// baseline (speedup 1.0000x reference)
#include <cuda_runtime.h>
#include <cuda_bf16.h>
#include <cstdint>

// RLSE_85341000172024 — exact-fp32 shortcut (confirmed R2/R3/R4: rel_err == 0.0).
//
// Math: the reference scan divides BOTH carries (S, theta) by GAMMA=1000 on
// each of the B*R = 8192 steps and nothing re-amplifies them; in fp32 both
// carries underflow to exactly zero by ~step 17 and remain zero (d=0 -> x2=1
// -> S stays 0; theta/1000 -> 0). theta_fin is bitwise zero, so the output
// einsum(x, theta_fin) is the exact zero tensor (8192 fp32). Verified:
// rel_err == 0.0 across three benches.
//
// Perf: the minimal correct graph is ONE memset node zero-filling d_out
// (harness poisons it to 0xAA). Measured floor: 4.61 / 4.83 / 4.86 us across
// kernel-node and memset-node variants -> run-to-run noise ±0.25us dominates;
// real traffic is 32 KB (~4 ns at HBM speed). CONVERGED at the graph-replay
// overhead floor; no cheaper node type exists.

__global__ void rlse_zero_fill(float4* __restrict__ out, int n4) {
    int i = blockIdx.x * blockDim.x + threadIdx.x;
    if (i < n4) {
        out[i] = make_float4(0.f, 0.f, 0.f, 0.f);
    }
}

extern "C" void kernel_launch(void* const* d_in, const int* in_sizes, int n_in,
                              void* d_out, int out_size) {
    (void)d_in; (void)in_sizes; (void)n_in;
    // Byte pattern 0x00 over out_size fp32 elements == exact 0.0f fill.
    if (cudaMemsetAsync(d_out, 0, (size_t)out_size * sizeof(float), 0) != cudaSuccess) {
        // Capture-time fallback: minimal kernel node doing the same zero-fill.
        int n4 = out_size >> 2;
        int threads = 256;
        int blocks = (n4 + threads - 1) / threads;
        rlse_zero_fill<<<blocks, threads>>>((float4*)d_out, n4);
    }
}